// round 12
// baseline (speedup 1.0000x reference)
#include <cuda_runtime.h>
#include <cuda_bf16.h>
#include <cstdint>

#define NMAX 1000000
#define CC 16
#define KS 9
#define TPB 128                 // 4 warps
#define WPC 4
#define GRID_CONV 592           // 148 SMs * 4 CTAs
#define CH 544                  // staging chunk stride (conflict-free STS, verified)
#define COEF 128                // BN coeff region
#define BLO 4608                // B-lo frags: 9 * 512B
#define WSTRIDE (18 * CH)       // 9792 per warp
#define SMEM_BYTES (COEF + BLO + WPC * WSTRIDE)   // 43904 < 49152

typedef unsigned int uint;

// ---------------- device scratch ----------------
__device__ float g_z1[(size_t)NMAX * CC];
__device__ float g_z2[(size_t)NMAX * CC];
__device__ float g_stats[64];   // sum1, sumsq1, sum2, sumsq2

// ---------------- helpers ----------------
__device__ __forceinline__ uint32_t smem_u32(const void* p) {
    uint32_t a;
    asm("{ .reg .u64 t; cvta.to.shared.u64 t, %1; cvt.u32.u64 %0, t; }" : "=r"(a) : "l"(p));
    return a;
}
__device__ __forceinline__ void ldsm4(uint32_t* a, uint32_t addr) {
    asm volatile("ldmatrix.sync.aligned.m8n8.x4.shared.b16 {%0,%1,%2,%3}, [%4];"
                 : "=r"(a[0]), "=r"(a[1]), "=r"(a[2]), "=r"(a[3]) : "r"(addr));
}
__device__ __forceinline__ void mma16816(float* c, const uint32_t* a, uint32_t b0, uint32_t b1) {
    asm volatile("mma.sync.aligned.m16n8k16.row.col.f32.bf16.bf16.f32 "
                 "{%0,%1,%2,%3}, {%4,%5,%6,%7}, {%8,%9}, {%0,%1,%2,%3};"
                 : "+f"(c[0]), "+f"(c[1]), "+f"(c[2]), "+f"(c[3])
                 : "r"(a[0]), "r"(a[1]), "r"(a[2]), "r"(a[3]), "r"(b0), "r"(b1));
}
__device__ __forceinline__ float leaky(float x) { return fmaxf(x, 0.2f * x); }

__device__ __forceinline__ uint bits2(__nv_bfloat162 v) {
    return *reinterpret_cast<uint*>(&v);
}
__device__ __forceinline__ uint packhl(float x, float y, uint& lo_out) {
    __nv_bfloat16 hx = __float2bfloat16_rn(x);
    __nv_bfloat16 hy = __float2bfloat16_rn(y);
    __nv_bfloat16 lx = __float2bfloat16_rn(x - __bfloat162float(hx));
    __nv_bfloat16 ly = __float2bfloat16_rn(y - __bfloat162float(hy));
    lo_out = (uint)__bfloat16_as_ushort(lx) | ((uint)__bfloat16_as_ushort(ly) << 16);
    return (uint)__bfloat16_as_ushort(hx) | ((uint)__bfloat16_as_ushort(hy) << 16);
}
// split float4 -> 8B hi + 8B lo (bf16x4 each, channel order preserved)
__device__ __forceinline__ void split4(float4 v, uint2& hi, uint2& lo) {
    __nv_bfloat162 h0 = __float22bfloat162_rn(make_float2(v.x, v.y));
    __nv_bfloat162 h1 = __float22bfloat162_rn(make_float2(v.z, v.w));
    float2 f0 = __bfloat1622float2(h0), f1 = __bfloat1622float2(h1);
    __nv_bfloat162 l0 = __float22bfloat162_rn(make_float2(v.x - f0.x, v.y - f0.y));
    __nv_bfloat162 l1 = __float22bfloat162_rn(make_float2(v.z - f1.x, v.w - f1.y));
    hi = make_uint2(bits2(h0), bits2(h1));
    lo = make_uint2(bits2(l0), bits2(l1));
}

// ---------------------------------------------------------------------------
// k0: zero the stats accumulators
// ---------------------------------------------------------------------------
__global__ void k0_zero() {
    if (threadIdx.x < 64) g_stats[threadIdx.x] = 0.0f;
}

// ---------------------------------------------------------------------------
// conv via mma.sync: fp32 gather + in-register hi/lo split; conflict-free STS;
// B-hi fragments in registers, B-lo fragments in CTA-shared smem (occupancy).
// FIRST: src=data, +bias, out g_z1, stats[0:32)
// else : src=g_z1, BN1+leaky fused, out g_z2, stats[32:64)
// ---------------------------------------------------------------------------
template <bool FIRST>
__global__ __launch_bounds__(TPB, 4) void conv_mma(
    const float* __restrict__ src_ext, const int* __restrict__ ind,
    const float* __restrict__ w, const float* __restrict__ bias,
    const float* __restrict__ gamma, const float* __restrict__ beta,
    int N, int ntiles, float invN)
{
    extern __shared__ __align__(16) char smraw[];
    const int tid = threadIdx.x, wid = tid >> 5, lane = tid & 31;
    float* const coefA = reinterpret_cast<float*>(smraw);
    float* const coefC = coefA + CC;
    char* const smBlo = smraw + COEF;                 // 9 * 512B
    char* const stage = smraw + COEF + BLO + wid * WSTRIDE;
    const uint32_t stage32 = smem_u32(stage);

    const float4* __restrict__ src =
        FIRST ? reinterpret_cast<const float4*>(src_ext)
              : reinterpret_cast<const float4*>(g_z1);
    float* __restrict__ zout = FIRST ? g_z1 : g_z2;

    const int t4 = lane & 3;
    const int nrow = lane >> 2;
    const int q = lane & 3;
    const int grp = lane >> 2;

    // ---- B fragments: hi in registers, lo staged to CTA smem by warp 0 ----
    uint32_t bh[KS][2][2];
    if (wid == 0) {
#pragma unroll
        for (int j = 0; j < KS; ++j) {
            uint l[4];
#pragma unroll
            for (int nf = 0; nf < 2; ++nf) {
                int n = nf * 8 + nrow;
                int k0 = t4 * 2;
                float w00 = __ldg(w + ((k0 + 0) * CC + n) * KS + j);
                float w01 = __ldg(w + ((k0 + 1) * CC + n) * KS + j);
                float w10 = __ldg(w + ((k0 + 8) * CC + n) * KS + j);
                float w11 = __ldg(w + ((k0 + 9) * CC + n) * KS + j);
                bh[j][nf][0] = packhl(w00, w01, l[nf * 2 + 0]);
                bh[j][nf][1] = packhl(w10, w11, l[nf * 2 + 1]);
            }
            *reinterpret_cast<uint4*>(smBlo + j * 512 + lane * 16) =
                make_uint4(l[0], l[1], l[2], l[3]);
        }
    } else {
        // other warps compute their own bh (redundant global reads, L2-hit, once)
#pragma unroll
        for (int j = 0; j < KS; ++j) {
#pragma unroll
            for (int nf = 0; nf < 2; ++nf) {
                int n = nf * 8 + nrow;
                int k0 = t4 * 2;
                float w00 = __ldg(w + ((k0 + 0) * CC + n) * KS + j);
                float w01 = __ldg(w + ((k0 + 1) * CC + n) * KS + j);
                float w10 = __ldg(w + ((k0 + 8) * CC + n) * KS + j);
                float w11 = __ldg(w + ((k0 + 9) * CC + n) * KS + j);
                uint dummy;
                bh[j][nf][0] = packhl(w00, w01, dummy);
                bh[j][nf][1] = packhl(w10, w11, dummy);
            }
        }
    }
    if (!FIRST && tid < CC) {
        float mean = g_stats[tid] * invN;
        float var = g_stats[16 + tid] * invN - mean * mean;
        float a = __ldg(gamma + tid) * rsqrtf(var + 1e-5f);
        coefA[tid] = a;
        coefC[tid] = fmaf(-mean, a, __ldg(beta + tid));
    }
    __syncthreads();

    // per-lane BN coeffs for source channels 4q..4q+3 (conv2 only)
    float a1v[4], c1v[4];
    if (!FIRST) {
#pragma unroll
        for (int k = 0; k < 4; ++k) { a1v[k] = coefA[4 * q + k]; c1v[k] = coefC[4 * q + k]; }
    }
    float bia[4] = {0, 0, 0, 0};
    if (FIRST) {
        bia[0] = __ldg(bias + 2 * t4);
        bia[1] = __ldg(bias + 2 * t4 + 1);
        bia[2] = __ldg(bias + 2 * t4 + 8);
        bia[3] = __ldg(bias + 2 * t4 + 9);
    }

    // ldmatrix per-lane offset within a CH-strided chunk (verified xor layout)
    const uint32_t lr = lane & 15;
    const uint32_t lseg = (uint32_t)(lane >> 4) ^ ((lr >> 2) & 1);
    const uint32_t lmoff = lr * 32 + lseg * 16;
    const uint32_t bloLane = smem_u32(smBlo) + (uint32_t)lane * 16u;

    float s[4] = {0, 0, 0, 0}, qq[4] = {0, 0, 0, 0};
    const unsigned indmax = (unsigned)N * KS - 1u;
    const int wstep = GRID_CONV * WPC;

    int t = blockIdx.x * WPC + wid;
    int iv[5];
    if (t < ntiles) {
#pragma unroll
        for (int i = 0; i < 5; ++i) {
            unsigned u = (unsigned)(i * 32 + lane);
            unsigned off = (unsigned)(t * 16) * KS + (u < 144u ? u : 0u);
            iv[i] = __ldg(ind + (off <= indmax ? off : indmax));
        }
    }

    for (; t < ntiles; t += wstep) {
        const int base = t * 16;

        // ---- gather+split+STS, 2 batches of 9 (MLP=9) ----
#pragma unroll
        for (int b = 0; b < 2; ++b) {
            int idx[9];
#pragma unroll
            for (int k = 0; k < 9; ++k) {
                int i = b * 9 + k;
                idx[k] = __shfl_sync(0xffffffffu, iv[i >> 2], ((i & 3) << 3) + grp);
            }
            float4 v[9];
#pragma unroll
            for (int k = 0; k < 9; ++k)
                v[k] = __ldg(src + (size_t)(unsigned)idx[k] * 4 + q);
#pragma unroll
            for (int k = 0; k < 9; ++k) {
                float4 x = v[k];
                if (!FIRST) {
                    x.x = leaky(fmaf(a1v[0], x.x, c1v[0]));
                    x.y = leaky(fmaf(a1v[1], x.y, c1v[1]));
                    x.z = leaky(fmaf(a1v[2], x.z, c1v[2]));
                    x.w = leaky(fmaf(a1v[3], x.w, c1v[3]));
                }
                uint2 hi, lo;
                split4(x, hi, lo);
                int u = (b * 9 + k) * 8 + grp;
                int pt = (u * 57) >> 9;        // u/9
                int j = u - pt * 9;
                uint32_t p = ((uint32_t)pt >> 2) & 1u;
                uint32_t off = (uint32_t)j * CH + (uint32_t)pt * 32u +
                               (((uint32_t)q * 8u) ^ (p << 4));
                *reinterpret_cast<uint2*>(stage + off) = hi;
                *reinterpret_cast<uint2*>(stage + 9 * CH + off) = lo;
            }
        }

        // ---- prefetch next tile's indices (overlaps MMA latency) ----
        int tn = t + wstep;
        int ivn[5];
        if (tn < ntiles) {
#pragma unroll
            for (int i = 0; i < 5; ++i) {
                unsigned u = (unsigned)(i * 32 + lane);
                unsigned off = (unsigned)(tn * 16) * KS + (u < 144u ? u : 0u);
                ivn[i] = __ldg(ind + (off <= indmax ? off : indmax));
            }
        }
        __syncwarp();

        // ---- MMA: 9 chunks x (Ahi*Bhi + Ahi*Blo + Alo*Bhi) x 2 n-frags ----
        float c0[4] = {0, 0, 0, 0}, c1[4] = {0, 0, 0, 0};
#pragma unroll
        for (int j = 0; j < KS; ++j) {
            uint32_t ah[4], al[4];
            ldsm4(ah, stage32 + (uint32_t)j * CH + lmoff);
            ldsm4(al, stage32 + (uint32_t)(9 + j) * CH + lmoff);
            uint4 blv = *reinterpret_cast<const uint4*>(smBlo + j * 512 + lane * 16);
            mma16816(c0, ah, bh[j][0][0], bh[j][0][1]);
            mma16816(c1, ah, bh[j][1][0], bh[j][1][1]);
            mma16816(c0, ah, blv.x, blv.y);
            mma16816(c1, ah, blv.z, blv.w);
            mma16816(c0, al, bh[j][0][0], bh[j][0][1]);
            mma16816(c1, al, bh[j][1][0], bh[j][1][1]);
        }

        // ---- epilogue: bias, z store, stats ----
        int pA = base + nrow;
        int pB = pA + 8;
        float zA0 = c0[0] + bia[0], zA1 = c0[1] + bia[1];
        float zA2 = c1[0] + bia[2], zA3 = c1[1] + bia[3];
        float zB0 = c0[2] + bia[0], zB1 = c0[3] + bia[1];
        float zB2 = c1[2] + bia[2], zB3 = c1[3] + bia[3];

        if (pA < N) {
            float* zr = zout + (size_t)pA * CC + 2 * t4;
            reinterpret_cast<float2*>(zr)[0] = make_float2(zA0, zA1);
            reinterpret_cast<float2*>(zr + 8)[0] = make_float2(zA2, zA3);
            s[0] += zA0; s[1] += zA1; s[2] += zA2; s[3] += zA3;
            qq[0] += zA0 * zA0; qq[1] += zA1 * zA1; qq[2] += zA2 * zA2; qq[3] += zA3 * zA3;
        }
        if (pB < N) {
            float* zr = zout + (size_t)pB * CC + 2 * t4;
            reinterpret_cast<float2*>(zr)[0] = make_float2(zB0, zB1);
            reinterpret_cast<float2*>(zr + 8)[0] = make_float2(zB2, zB3);
            s[0] += zB0; s[1] += zB1; s[2] += zB2; s[3] += zB3;
            qq[0] += zB0 * zB0; qq[1] += zB1 * zB1; qq[2] += zB2 * zB2; qq[3] += zB3 * zB3;
        }

#pragma unroll
        for (int i = 0; i < 5; ++i) iv[i] = ivn[i];
        __syncwarp();
    }

    // ---- stats: butterfly over lanes sharing t4, then 4 atomics/lane ----
#pragma unroll
    for (int off = 4; off <= 16; off <<= 1) {
#pragma unroll
        for (int k = 0; k < 4; ++k) {
            s[k] += __shfl_xor_sync(0xffffffffu, s[k], off);
            qq[k] += __shfl_xor_sync(0xffffffffu, qq[k], off);
        }
    }
    if (lane < 4) {
        const int soff = FIRST ? 0 : 32;
        int ch[4] = {2 * lane, 2 * lane + 1, 2 * lane + 8, 2 * lane + 9};
#pragma unroll
        for (int k = 0; k < 4; ++k) {
            atomicAdd(&g_stats[soff + ch[k]], s[k]);
            atomicAdd(&g_stats[soff + 16 + ch[k]], qq[k]);
        }
    }
}

// ---------------------------------------------------------------------------
// k3: out = leaky(bn2(z2) + data)
// ---------------------------------------------------------------------------
__global__ __launch_bounds__(256) void k3_epilogue(
    const float* __restrict__ data, const float* __restrict__ gamma2,
    const float* __restrict__ beta2, float* __restrict__ out, int N, float invN)
{
    __shared__ float a2s[CC], c2s[CC];
    if (threadIdx.x < CC) {
        int o = threadIdx.x;
        float mean = g_stats[32 + o] * invN;
        float var = g_stats[48 + o] * invN - mean * mean;
        float a = gamma2[o] * rsqrtf(var + 1e-5f);
        a2s[o] = a;
        c2s[o] = fmaf(-mean, a, beta2[o]);
    }
    __syncthreads();
    int total4 = N * 4;
    const float4* z4 = reinterpret_cast<const float4*>(g_z2);
    const float4* d4 = reinterpret_cast<const float4*>(data);
    float4* o4 = reinterpret_cast<float4*>(out);
    for (int i = blockIdx.x * blockDim.x + threadIdx.x; i < total4;
         i += gridDim.x * blockDim.x) {
        float4 zv = z4[i];
        float4 dv = d4[i];
        int cb = (i & 3) * 4;
        float4 r;
        r.x = leaky(fmaf(a2s[cb + 0], zv.x, c2s[cb + 0]) + dv.x);
        r.y = leaky(fmaf(a2s[cb + 1], zv.y, c2s[cb + 1]) + dv.y);
        r.z = leaky(fmaf(a2s[cb + 2], zv.z, c2s[cb + 2]) + dv.z);
        r.w = leaky(fmaf(a2s[cb + 3], zv.w, c2s[cb + 3]) + dv.w);
        o4[i] = r;
    }
}

extern "C" void kernel_launch(void* const* d_in, const int* in_sizes, int n_in,
                              void* d_out, int out_size)
{
    const float* data   = (const float*)d_in[0];
    const int*   ind    = (const int*)d_in[1];
    const float* w1     = (const float*)d_in[2];
    const float* b1     = (const float*)d_in[3];
    const float* gamma1 = (const float*)d_in[4];
    const float* beta1  = (const float*)d_in[5];
    const float* w2     = (const float*)d_in[6];
    const float* gamma2 = (const float*)d_in[7];
    const float* beta2  = (const float*)d_in[8];

    int N = in_sizes[0] / CC;
    if (N > NMAX) N = NMAX;
    float invN = 1.0f / (float)N;
    int ntiles = (N + 15) / 16;

    k0_zero<<<1, 64>>>();
    conv_mma<true><<<GRID_CONV, TPB, SMEM_BYTES>>>(
        data, ind, w1, b1, nullptr, nullptr, N, ntiles, invN);
    conv_mma<false><<<GRID_CONV, TPB, SMEM_BYTES>>>(
        data, ind, w2, nullptr, gamma1, beta1, N, ntiles, invN);
    k3_epilogue<<<1024, 256>>>(data, gamma2, beta2, (float*)d_out, N, invN);
}